// round 1
// baseline (speedup 1.0000x reference)
#include <cuda_runtime.h>
#include <cstddef>

// Problem dims
#define BB   4096
#define TT   256
#define NI   38
#define IP   40      // padded input width
#define H1R  50
#define H1P  64      // padded H1
#define H2R  15
#define H2P  16      // padded H2
#define NCLS 14
#define K1   (IP + H1P)    // 104
#define K2   (H1P + H2P)   // 80
#define ROWS 32            // batch rows per CTA
#define NTH  256
#define BUFW 132           // xh row stride (floats): [0,40)=x [40,104)=h1 [104,120)=h2, pad

struct SMem {
    float4 w1[K1][64];    // layer1 weights, packed (i,f,g,o) per column j, 106496 B
    float4 w2[K2][16];    // layer2 weights, packed, 20480 B
    float4 b1[64];        // b_ih1+b_hh1 packed per gate-quad
    float4 b2[16];
    float  wfc[NCLS][16];
    float  bfc[16];
    float  xh[ROWS][BUFW]; // per-row activations: x | h1 | h2
};

__device__ __forceinline__ float sigf(float x)  { return 1.0f / (1.0f + __expf(-x)); }
__device__ __forceinline__ float tanhf_(float x){ return 2.0f / (1.0f + __expf(-2.0f * x)) - 1.0f; }

__global__ __launch_bounds__(NTH, 1)
void lstm_fused_kernel(const float* __restrict__ x,
                       const float* __restrict__ w_ih1, const float* __restrict__ w_hh1,
                       const float* __restrict__ b_ih1, const float* __restrict__ b_hh1,
                       const float* __restrict__ w_ih2, const float* __restrict__ w_hh2,
                       const float* __restrict__ b_ih2, const float* __restrict__ b_hh2,
                       const float* __restrict__ w_fc,  const float* __restrict__ b_fc,
                       float* __restrict__ out)
{
    extern __shared__ char smem_raw[];
    SMem* s = reinterpret_cast<SMem*>(smem_raw);
    const int tid = threadIdx.x;
    const int rowbase = blockIdx.x * ROWS;

    // ---------------- one-time shared fill ----------------
    // layer1 weights: w1[k][j] = (Wi[j][k'], Wi[50+j][k'], Wi[100+j][k'], Wi[150+j][k'])
    for (int idx = tid; idx < K1 * 64; idx += NTH) {
        int k = idx >> 6, j = idx & 63;
        float4 v = make_float4(0.f, 0.f, 0.f, 0.f);
        if (j < H1R) {
            if (k < IP) {
                if (k < NI) {
                    v.x = w_ih1[(0 * H1R + j) * NI + k];
                    v.y = w_ih1[(1 * H1R + j) * NI + k];
                    v.z = w_ih1[(2 * H1R + j) * NI + k];
                    v.w = w_ih1[(3 * H1R + j) * NI + k];
                }
            } else {
                int kk = k - IP;
                if (kk < H1R) {
                    v.x = w_hh1[(0 * H1R + j) * H1R + kk];
                    v.y = w_hh1[(1 * H1R + j) * H1R + kk];
                    v.z = w_hh1[(2 * H1R + j) * H1R + kk];
                    v.w = w_hh1[(3 * H1R + j) * H1R + kk];
                }
            }
        }
        s->w1[k][j] = v;
    }
    // layer2 weights: k in [0,64) -> h1 input (real K=50), k in [64,80) -> h2 recurrent (real 15)
    for (int idx = tid; idx < K2 * 16; idx += NTH) {
        int k = idx >> 4, j = idx & 15;
        float4 v = make_float4(0.f, 0.f, 0.f, 0.f);
        if (j < H2R) {
            if (k < H1P) {
                if (k < H1R) {
                    v.x = w_ih2[(0 * H2R + j) * H1R + k];
                    v.y = w_ih2[(1 * H2R + j) * H1R + k];
                    v.z = w_ih2[(2 * H2R + j) * H1R + k];
                    v.w = w_ih2[(3 * H2R + j) * H1R + k];
                }
            } else {
                int kk = k - H1P;
                if (kk < H2R) {
                    v.x = w_hh2[(0 * H2R + j) * H2R + kk];
                    v.y = w_hh2[(1 * H2R + j) * H2R + kk];
                    v.z = w_hh2[(2 * H2R + j) * H2R + kk];
                    v.w = w_hh2[(3 * H2R + j) * H2R + kk];
                }
            }
        }
        s->w2[k][j] = v;
    }
    // biases (b_ih + b_hh), packed per gate-quad
    for (int j = tid; j < 64; j += NTH) {
        float4 v = make_float4(0.f, 0.f, 0.f, 0.f);
        if (j < H1R) {
            v.x = b_ih1[0 * H1R + j] + b_hh1[0 * H1R + j];
            v.y = b_ih1[1 * H1R + j] + b_hh1[1 * H1R + j];
            v.z = b_ih1[2 * H1R + j] + b_hh1[2 * H1R + j];
            v.w = b_ih1[3 * H1R + j] + b_hh1[3 * H1R + j];
        }
        s->b1[j] = v;
    }
    if (tid < 16) {
        int j = tid;
        float4 v = make_float4(0.f, 0.f, 0.f, 0.f);
        if (j < H2R) {
            v.x = b_ih2[0 * H2R + j] + b_hh2[0 * H2R + j];
            v.y = b_ih2[1 * H2R + j] + b_hh2[1 * H2R + j];
            v.z = b_ih2[2 * H2R + j] + b_hh2[2 * H2R + j];
            v.w = b_ih2[3 * H2R + j] + b_hh2[3 * H2R + j];
        }
        s->b2[j] = v;
    }
    for (int idx = tid; idx < NCLS * 16; idx += NTH) {
        int n = idx >> 4, k = idx & 15;
        s->wfc[n][k] = (k < H2R) ? w_fc[n * H2R + k] : 0.f;
    }
    if (tid < 16) s->bfc[tid] = (tid < NCLS) ? b_fc[tid] : 0.f;
    // zero activation buffer (h0 = 0, pads = 0)
    for (int idx = tid; idx < ROWS * BUFW; idx += NTH)
        (&s->xh[0][0])[idx] = 0.f;

    // ---------------- per-thread mappings ----------------
    const int jq  = tid & 63;          // layer1 gate-quad column 0..63
    const int rb  = tid >> 6;          // layer1 row block (8 rows)
    const int r1b = rb * 8;
    const int j2  = tid & 15;          // layer2 gate-quad column 0..15
    const int rb2 = tid >> 4;          // layer2 row block (2 rows)
    const int r2b = rb2 * 2;

    float c1[8];
    #pragma unroll
    for (int r = 0; r < 8; r++) c1[r] = 0.f;
    float c2[2] = {0.f, 0.f};

    __syncthreads();

    // ---------------- time loop ----------------
    for (int t = 0; t < TT; t++) {
        // load x tile for this timestep into cols [0,40)
        for (int idx = tid; idx < ROWS * IP; idx += NTH) {
            int r = idx / IP, col = idx - r * IP;
            float v = 0.f;
            if (col < NI)
                v = x[((long)(rowbase + r) * TT + t) * NI + col];
            s->xh[r][col] = v;
        }
        __syncthreads();   // x ready; also orders prev-step h2 writes before this step's L2 reads

        // ---- layer1 GEMM: gates[r][jq quad] over K1=104 (x + h1_prev) ----
        float4 acc[8];
        #pragma unroll
        for (int r = 0; r < 8; r++) acc[r] = s->b1[jq];
        #pragma unroll 1
        for (int k = 0; k < K1; k += 4) {
            float4 wa = s->w1[k + 0][jq];
            float4 wb = s->w1[k + 1][jq];
            float4 wc = s->w1[k + 2][jq];
            float4 wd = s->w1[k + 3][jq];
            #pragma unroll
            for (int r = 0; r < 8; r++) {
                float4 h = *reinterpret_cast<const float4*>(&s->xh[r1b + r][k]);
                acc[r].x = fmaf(wa.x, h.x, fmaf(wb.x, h.y, fmaf(wc.x, h.z, fmaf(wd.x, h.w, acc[r].x))));
                acc[r].y = fmaf(wa.y, h.x, fmaf(wb.y, h.y, fmaf(wc.y, h.z, fmaf(wd.y, h.w, acc[r].y))));
                acc[r].z = fmaf(wa.z, h.x, fmaf(wb.z, h.y, fmaf(wc.z, h.z, fmaf(wd.z, h.w, acc[r].z))));
                acc[r].w = fmaf(wa.w, h.x, fmaf(wb.w, h.y, fmaf(wc.w, h.z, fmaf(wd.w, h.w, acc[r].w))));
            }
        }
        __syncthreads();   // all reads of h1_prev done before overwriting h1

        // ---- layer1 state update; write new h1 into cols [40,104) ----
        #pragma unroll
        for (int r = 0; r < 8; r++) {
            float ig = sigf(acc[r].x);
            float fg = sigf(acc[r].y);
            float gg = tanhf_(acc[r].z);
            float og = sigf(acc[r].w);
            float c  = fmaf(fg, c1[r], ig * gg);
            c1[r] = c;
            s->xh[r1b + r][IP + jq] = og * tanhf_(c);
        }
        __syncthreads();   // h1_t ready for layer2

        // ---- layer2 GEMM over K2=80 (h1_t + h2_prev), cols [40,120) ----
        float4 a2[2];
        a2[0] = s->b2[j2];
        a2[1] = s->b2[j2];
        #pragma unroll 1
        for (int k = 0; k < K2; k += 4) {
            float4 wa = s->w2[k + 0][j2];
            float4 wb = s->w2[k + 1][j2];
            float4 wc = s->w2[k + 2][j2];
            float4 wd = s->w2[k + 3][j2];
            #pragma unroll
            for (int r = 0; r < 2; r++) {
                float4 h = *reinterpret_cast<const float4*>(&s->xh[r2b + r][IP + k]);
                a2[r].x = fmaf(wa.x, h.x, fmaf(wb.x, h.y, fmaf(wc.x, h.z, fmaf(wd.x, h.w, a2[r].x))));
                a2[r].y = fmaf(wa.y, h.x, fmaf(wb.y, h.y, fmaf(wc.y, h.z, fmaf(wd.y, h.w, a2[r].y))));
                a2[r].z = fmaf(wa.z, h.x, fmaf(wb.z, h.y, fmaf(wc.z, h.z, fmaf(wd.z, h.w, a2[r].z))));
                a2[r].w = fmaf(wa.w, h.x, fmaf(wb.w, h.y, fmaf(wc.w, h.z, fmaf(wd.w, h.w, a2[r].w))));
            }
        }
        __syncthreads();   // all reads of h2_prev done before overwriting h2

        // ---- layer2 state update; write new h2 into cols [104,120) ----
        #pragma unroll
        for (int r = 0; r < 2; r++) {
            float ig = sigf(a2[r].x);
            float fg = sigf(a2[r].y);
            float gg = tanhf_(a2[r].z);
            float og = sigf(a2[r].w);
            float c  = fmaf(fg, c2[r], ig * gg);
            c2[r] = c;
            s->xh[r2b + r][IP + H1P + j2] = og * tanhf_(c);
        }
        // next iteration's first __syncthreads() orders these writes vs next L2 reads
    }

    __syncthreads();

    // ---------------- final FC on h2(T-1) ----------------
    for (int idx = tid; idx < ROWS * NCLS; idx += NTH) {
        int r = idx / NCLS, n = idx - r * NCLS;
        float a = s->bfc[n];
        #pragma unroll
        for (int k = 0; k < H2P; k++)
            a = fmaf(s->xh[r][IP + H1P + k], s->wfc[n][k], a);
        out[(long)(rowbase + r) * NCLS + n] = a;
    }
}

extern "C" void kernel_launch(void* const* d_in, const int* in_sizes, int n_in,
                              void* d_out, int out_size)
{
    const float* x     = (const float*)d_in[0];
    const float* w_ih1 = (const float*)d_in[1];
    const float* w_hh1 = (const float*)d_in[2];
    const float* b_ih1 = (const float*)d_in[3];
    const float* b_hh1 = (const float*)d_in[4];
    const float* w_ih2 = (const float*)d_in[5];
    const float* w_hh2 = (const float*)d_in[6];
    const float* b_ih2 = (const float*)d_in[7];
    const float* b_hh2 = (const float*)d_in[8];
    const float* w_fc  = (const float*)d_in[9];
    const float* b_fc  = (const float*)d_in[10];
    float* out = (float*)d_out;

    const size_t smem_bytes = sizeof(SMem);
    cudaFuncSetAttribute(lstm_fused_kernel,
                         cudaFuncAttributeMaxDynamicSharedMemorySize,
                         (int)smem_bytes);

    lstm_fused_kernel<<<BB / ROWS, NTH, smem_bytes>>>(
        x, w_ih1, w_hh1, b_ih1, b_hh1,
        w_ih2, w_hh2, b_ih2, b_hh2, w_fc, b_fc, out);
}

// round 3
// speedup vs baseline: 1.2422x; 1.2422x over previous
#include <cuda_runtime.h>

// Dims
#define TT   256
#define NI   38
#define H1   50
#define H2   15
#define NCLS 14
#define K1   88        // NI + H1 (exact)
#define K2   68        // [col36..col103]: 2 zero-pad + 50 h1 + 15 h2 + 1 zero-pad
#define ROWS 32        // batch rows per CTA = lanes
#define NTH  512
#define BUFW 108       // xh row stride floats = 432B = 27*16B (LDS.128-aligned, conflict-free)
#define NK1  44        // K1/2 pairs
#define NK2  34        // K2/2 pairs
#define L2C0 36        // layer2 K window starts at col 36 (16B aligned)
#define NLOAD (ROWS*NI)

// w1p[kk][unit][0] = (wi[2kk],wi[2kk+1], wf[2kk],wf[2kk+1])
// w1p[kk][unit][1] = (wg[2kk],wg[2kk+1], wo[2kk],wo[2kk+1])
struct SMem {
    float4 w1p[NK1][64][2];   // 90112 B
    float4 w2p[NK2][16][2];   // 17408 B
    float4 b1q[64];
    float4 b2q[16];
    float  wfc[NCLS][16];
    float  bfc[16];
    float  xh[ROWS][BUFW];    // [0,38) x | [38,88) h1 | [88,103) h2 | 103+ pad
};

__device__ __forceinline__ void fma2(unsigned long long& d,
                                     unsigned long long a, unsigned long long b) {
    asm("fma.rn.f32x2 %0, %1, %2, %0;" : "+l"(d) : "l"(a), "l"(b));
}
__device__ __forceinline__ float fold2(unsigned long long v) {
    float lo, hi;
    asm("mov.b64 {%0,%1}, %2;" : "=f"(lo), "=f"(hi) : "l"(v));
    return lo + hi;
}
__device__ __forceinline__ float sigf(float x)  { return 1.0f / (1.0f + __expf(-x)); }
__device__ __forceinline__ float tanhf_(float x){ return 2.0f / (1.0f + __expf(-2.0f * x)) - 1.0f; }

__device__ __forceinline__ unsigned long long lo2(float4 v) {
    return *reinterpret_cast<const unsigned long long*>(&v.x);
}
__device__ __forceinline__ unsigned long long hi2(float4 v) {
    return *reinterpret_cast<const unsigned long long*>(&v.z);
}

// host-layout fetch helpers (torch [4H, Kin], gate order i,f,g,o)
__device__ __forceinline__ float wv1(const float* wih, const float* whh,
                                     int g, int j, int k) {
    if (j >= H1) return 0.f;
    if (k < NI) return wih[(g * H1 + j) * NI + k];
    return whh[(g * H1 + j) * H1 + (k - NI)];
}
// layer2 k index is over cols [36..104): k2=0,1 -> zero; 2..51 -> h1; 52..66 -> h2; 67 -> zero
__device__ __forceinline__ float wv2(const float* wih, const float* whh,
                                     int g, int j, int k2) {
    if (j >= H2) return 0.f;
    int k = k2 - 2;
    if (k < 0 || k >= H1 + H2) return 0.f;
    if (k < H1) return wih[(g * H2 + j) * H1 + k];
    return whh[(g * H2 + j) * H2 + (k - H1)];
}

__global__ __launch_bounds__(NTH, 1)
void lstm_fused_kernel(const float* __restrict__ x,
                       const float* __restrict__ w_ih1, const float* __restrict__ w_hh1,
                       const float* __restrict__ b_ih1, const float* __restrict__ b_hh1,
                       const float* __restrict__ w_ih2, const float* __restrict__ w_hh2,
                       const float* __restrict__ b_ih2, const float* __restrict__ b_hh2,
                       const float* __restrict__ w_fc,  const float* __restrict__ b_fc,
                       float* __restrict__ out)
{
    extern __shared__ char smem_raw[];
    SMem* s = reinterpret_cast<SMem*>(smem_raw);
    const int tid  = threadIdx.x;
    const int lane = tid & 31;       // batch row within CTA
    const int wid  = tid >> 5;       // 0..15
    const int q0   = wid * 4;        // layer1 units owned by this warp
    const int rowbase = blockIdx.x * ROWS;
    float* xh_flat = &s->xh[0][0];

    // ---------------- one-time shared fill ----------------
    for (int f = tid; f < NK1 * 64 * 2; f += NTH) {
        int kk = f >> 7, rem = f & 127, q = rem >> 1, hf = rem & 1;
        int g0 = hf * 2, k0 = 2 * kk;
        float4 v;
        v.x = wv1(w_ih1, w_hh1, g0,     q, k0);
        v.y = wv1(w_ih1, w_hh1, g0,     q, k0 + 1);
        v.z = wv1(w_ih1, w_hh1, g0 + 1, q, k0);
        v.w = wv1(w_ih1, w_hh1, g0 + 1, q, k0 + 1);
        s->w1p[kk][q][hf] = v;
    }
    for (int f = tid; f < NK2 * 16 * 2; f += NTH) {
        int kk = f >> 5, rem = f & 31, q = rem >> 1, hf = rem & 1;
        int g0 = hf * 2, k0 = 2 * kk;
        float4 v;
        v.x = wv2(w_ih2, w_hh2, g0,     q, k0);
        v.y = wv2(w_ih2, w_hh2, g0,     q, k0 + 1);
        v.z = wv2(w_ih2, w_hh2, g0 + 1, q, k0);
        v.w = wv2(w_ih2, w_hh2, g0 + 1, q, k0 + 1);
        s->w2p[kk][q][hf] = v;
    }
    for (int j = tid; j < 64; j += NTH) {
        float4 v = make_float4(0.f, 0.f, 0.f, 0.f);
        if (j < H1) {
            v.x = b_ih1[0*H1+j] + b_hh1[0*H1+j];
            v.y = b_ih1[1*H1+j] + b_hh1[1*H1+j];
            v.z = b_ih1[2*H1+j] + b_hh1[2*H1+j];
            v.w = b_ih1[3*H1+j] + b_hh1[3*H1+j];
        }
        s->b1q[j] = v;
    }
    if (tid < 16) {
        int j = tid;
        float4 v = make_float4(0.f, 0.f, 0.f, 0.f);
        if (j < H2) {
            v.x = b_ih2[0*H2+j] + b_hh2[0*H2+j];
            v.y = b_ih2[1*H2+j] + b_hh2[1*H2+j];
            v.z = b_ih2[2*H2+j] + b_hh2[2*H2+j];
            v.w = b_ih2[3*H2+j] + b_hh2[3*H2+j];
        }
        s->b2q[j] = v;
    }
    for (int f = tid; f < NCLS * 16; f += NTH) {
        int n = f >> 4, k = f & 15;
        s->wfc[n][k] = (k < H2) ? w_fc[n * H2 + k] : 0.f;
    }
    if (tid < 16) s->bfc[tid] = (tid < NCLS) ? b_fc[tid] : 0.f;
    for (int f = tid; f < ROWS * BUFW; f += NTH) xh_flat[f] = 0.f;

    // ---------------- x prefetch setup (3 slots/thread) ----------------
    const float* gp[3];
    int so[3];
    bool vld[3];
    float xr[3];
    #pragma unroll
    for (int sl = 0; sl < 3; sl++) {
        int idx = tid + sl * NTH;
        vld[sl] = (idx < NLOAD);
        int r = idx / NI, c = idx - r * NI;
        if (!vld[sl]) { r = 0; c = 0; }
        so[sl] = r * BUFW + c;
        int gbase = ((rowbase + r) * TT) * NI + c;
        if (vld[sl]) xh_flat[so[sl]] = x[gbase];              // x(t=0) -> smem
        gp[sl] = x + gbase + NI;
        xr[sl] = vld[sl] ? *gp[sl] : 0.f;                     // prefetch x(t=1)
        gp[sl] += NI;
    }

    float c1[4] = {0.f, 0.f, 0.f, 0.f};
    float c2 = 0.f;

    // ---------------- time loop ----------------
    for (int t = 0; t < TT; t++) {
        __syncthreads();   // sync1: x(t), h1(t-1), h2(t-1) visible

        // ---- layer1 GEMM: warp's 4 units x this lane's row, K=88 ----
        unsigned long long A[4][4];
        #pragma unroll
        for (int q = 0; q < 4; q++)
            #pragma unroll
            for (int g = 0; g < 4; g++) A[q][g] = 0ULL;

        const float4* hp4 = reinterpret_cast<const float4*>(&s->xh[lane][0]);
        #pragma unroll 2
        for (int kk2 = 0; kk2 < NK1 / 2; kk2++) {
            float4 h4 = hp4[kk2];
            unsigned long long ha = lo2(h4), hb = hi2(h4);
            #pragma unroll
            for (int q = 0; q < 4; q++) {
                ulonglong2 wa0 = *reinterpret_cast<const ulonglong2*>(&s->w1p[2*kk2][q0 + q][0]);
                ulonglong2 wb0 = *reinterpret_cast<const ulonglong2*>(&s->w1p[2*kk2][q0 + q][1]);
                fma2(A[q][0], wa0.x, ha);
                fma2(A[q][1], wa0.y, ha);
                fma2(A[q][2], wb0.x, ha);
                fma2(A[q][3], wb0.y, ha);
                ulonglong2 wa1 = *reinterpret_cast<const ulonglong2*>(&s->w1p[2*kk2+1][q0 + q][0]);
                ulonglong2 wb1 = *reinterpret_cast<const ulonglong2*>(&s->w1p[2*kk2+1][q0 + q][1]);
                fma2(A[q][0], wa1.x, hb);
                fma2(A[q][1], wa1.y, hb);
                fma2(A[q][2], wb1.x, hb);
                fma2(A[q][3], wb1.y, hb);
            }
        }
        __syncthreads();   // sync2: all reads of x(t), h1(t-1) complete

        // store x(t+1) into smem; prefetch x(t+2)
        if (t + 1 < TT) {
            #pragma unroll
            for (int sl = 0; sl < 3; sl++)
                if (vld[sl]) xh_flat[so[sl]] = xr[sl];
            if (t + 2 < TT) {
                #pragma unroll
                for (int sl = 0; sl < 3; sl++) {
                    if (vld[sl]) xr[sl] = *gp[sl];
                    gp[sl] += NI;
                }
            }
        }

        // ---- layer1 nonlinearity + h1 store (REAL units only) ----
        #pragma unroll
        for (int q = 0; q < 4; q++) {
            float4 b = s->b1q[q0 + q];
            float gi = fold2(A[q][0]) + b.x;
            float gf = fold2(A[q][1]) + b.y;
            float gg = fold2(A[q][2]) + b.z;
            float go = fold2(A[q][3]) + b.w;
            float ig = sigf(gi);
            float fg = sigf(gf);
            float cg = tanhf_(gg);
            float og = sigf(go);
            float c  = fmaf(fg, c1[q], ig * cg);
            c1[q] = c;
            if (q0 + q < H1)                       // <-- fix: pad units must not store
                s->xh[lane][NI + q0 + q] = og * tanhf_(c);
        }
        __syncthreads();   // sync3: h1(t) ready

        // ---- layer2 GEMM: warp's unit, K=68 over cols [36,104) ----
        unsigned long long B[4] = {0ULL, 0ULL, 0ULL, 0ULL};
        const float4* hp24 = reinterpret_cast<const float4*>(&s->xh[lane][L2C0]);
        #pragma unroll 2
        for (int kk2 = 0; kk2 < NK2 / 2; kk2++) {
            float4 h4 = hp24[kk2];
            unsigned long long ha = lo2(h4), hb = hi2(h4);
            ulonglong2 wa0 = *reinterpret_cast<const ulonglong2*>(&s->w2p[2*kk2][wid][0]);
            ulonglong2 wb0 = *reinterpret_cast<const ulonglong2*>(&s->w2p[2*kk2][wid][1]);
            fma2(B[0], wa0.x, ha);
            fma2(B[1], wa0.y, ha);
            fma2(B[2], wb0.x, ha);
            fma2(B[3], wb0.y, ha);
            ulonglong2 wa1 = *reinterpret_cast<const ulonglong2*>(&s->w2p[2*kk2+1][wid][0]);
            ulonglong2 wb1 = *reinterpret_cast<const ulonglong2*>(&s->w2p[2*kk2+1][wid][1]);
            fma2(B[0], wa1.x, hb);
            fma2(B[1], wa1.y, hb);
            fma2(B[2], wb1.x, hb);
            fma2(B[3], wb1.y, hb);
        }
        __syncthreads();   // sync4: all reads of h2(t-1) complete

        // ---- layer2 nonlinearity + h2 store (unit wid; wid 15 is inert pad) ----
        {
            float4 b = s->b2q[wid];
            float gi = fold2(B[0]) + b.x;
            float gf = fold2(B[1]) + b.y;
            float gg = fold2(B[2]) + b.z;
            float go = fold2(B[3]) + b.w;
            float ig = sigf(gi);
            float fg = sigf(gf);
            float cg = tanhf_(gg);
            float og = sigf(go);
            c2 = fmaf(fg, c2, ig * cg);
            if (wid < H2)
                s->xh[lane][NI + H1 + wid] = og * tanhf_(c2);
        }
    }

    __syncthreads();

    // ---------------- final FC on h2(T-1) ----------------
    if (tid < ROWS * NCLS) {
        int r = tid / NCLS, n = tid - r * NCLS;
        float a = s->bfc[n];
        #pragma unroll
        for (int k = 0; k < 15; k++)
            a = fmaf(s->xh[r][NI + H1 + k], s->wfc[n][k], a);
        out[(rowbase + r) * NCLS + n] = a;
    }
}

extern "C" void kernel_launch(void* const* d_in, const int* in_sizes, int n_in,
                              void* d_out, int out_size)
{
    const float* x     = (const float*)d_in[0];
    const float* w_ih1 = (const float*)d_in[1];
    const float* w_hh1 = (const float*)d_in[2];
    const float* b_ih1 = (const float*)d_in[3];
    const float* b_hh1 = (const float*)d_in[4];
    const float* w_ih2 = (const float*)d_in[5];
    const float* w_hh2 = (const float*)d_in[6];
    const float* b_ih2 = (const float*)d_in[7];
    const float* b_hh2 = (const float*)d_in[8];
    const float* w_fc  = (const float*)d_in[9];
    const float* b_fc  = (const float*)d_in[10];
    float* out = (float*)d_out;

    const size_t smem_bytes = sizeof(SMem);
    cudaFuncSetAttribute(lstm_fused_kernel,
                         cudaFuncAttributeMaxDynamicSharedMemorySize,
                         (int)smem_bytes);

    lstm_fused_kernel<<<4096 / ROWS, NTH, smem_bytes>>>(
        x, w_ih1, w_hh1, b_ih1, b_hh1,
        w_ih2, w_hh2, b_ih2, b_hh2, w_fc, b_fc, out);
}